// round 12
// baseline (speedup 1.0000x reference)
#include <cuda_runtime.h>
#include <cuda_fp16.h>
#include <cstdint>
#include <math.h>

#define B_  32
#define T_  2048
#define D_  1024
#define A_  1024

// ---------------- scratch ---------------------------------------------------
__device__ float  g_ws[B_ * A_];
__device__ float  g_scores[B_ * T_];
__device__ float  g_zinv[B_];
__device__ float  g_cpart[16 * B_ * D_];
__device__ __half g_h16[(size_t)B_ * T_ * D_];   // 128 MB
__device__ __half g_U16[(size_t)D_ * A_];        // 2 MB

// ---------------- helpers ---------------------------------------------------
__device__ __forceinline__ uint32_t smem_u32(const void* p) {
    uint32_t a;
    asm("{ .reg .u64 t; cvta.to.shared.u64 t, %1; cvt.u32.u64 %0, t; }" : "=r"(a) : "l"(p));
    return a;
}
__device__ __forceinline__ void cp_async16(uint32_t dst, const void* src) {
    asm volatile("cp.async.cg.shared.global [%0], [%1], 16;\n" :: "r"(dst), "l"(src) : "memory");
}
#define CP_COMMIT() asm volatile("cp.async.commit_group;\n" ::: "memory")
#define CP_WAIT0()  asm volatile("cp.async.wait_group 0;\n" ::: "memory")

__device__ __forceinline__ void ldsm_x4(uint32_t* r, uint32_t addr) {
    asm volatile("ldmatrix.sync.aligned.m8n8.x4.shared.b16 {%0,%1,%2,%3}, [%4];"
        : "=r"(r[0]), "=r"(r[1]), "=r"(r[2]), "=r"(r[3]) : "r"(addr));
}
__device__ __forceinline__ void ldsm_x4_t(uint32_t* r, uint32_t addr) {
    asm volatile("ldmatrix.sync.aligned.m8n8.x4.trans.shared.b16 {%0,%1,%2,%3}, [%4];"
        : "=r"(r[0]), "=r"(r[1]), "=r"(r[2]), "=r"(r[3]) : "r"(addr));
}
__device__ __forceinline__ void mma16816(float* c, const uint32_t* a, const uint32_t* b) {
    asm volatile(
        "mma.sync.aligned.m16n8k16.row.col.f32.f16.f16.f32 "
        "{%0,%1,%2,%3}, {%4,%5,%6,%7}, {%8,%9}, {%0,%1,%2,%3};"
        : "+f"(c[0]), "+f"(c[1]), "+f"(c[2]), "+f"(c[3])
        : "r"(a[0]), "r"(a[1]), "r"(a[2]), "r"(a[3]), "r"(b[0]), "r"(b[1]));
}
__device__ __forceinline__ float tanh_fast(float x) {
    float y;
    asm("tanh.approx.f32 %0, %1;" : "=f"(y) : "f"(x));
    return y;
}

// ---------------- smem layout (bytes) ---------------------------------------
#define NSTG     4
#define A_STRIDE 112
#define B_STRIDE 272
#define ASTG_SZ  (128 * A_STRIDE)                // 14336
#define BSTG_SZ  (32 * B_STRIDE)                 // 8704
#define AS_OFF   0
#define BS_OFF   (NSTG * ASTG_SZ)                // 57344
#define WS_OFF   (BS_OFF + NSTG * BSTG_SZ)       // 92160
#define VS_OFF   (WS_OFF + 4096)                 // 96256
#define SC_OFF   (VS_OFF + 4096)                 // 100352  (2 banks x 128 floats)
#define SMEM_SZ  (SC_OFF + 1024)                 // 101376

#define NG 256   // 8 a-tiles x 32 k-chunks

// stage chunk g = at*32 + kc  (128 threads: 4 iters of 128 for A and B each)
__device__ __forceinline__ void stage(char* sm, int g, const __half* __restrict__ h16row0,
                                      int tid) {
    const int sidx = g % NSTG;
    const int kc = g & 31, at = g >> 5;
    const int k0 = kc * 32;
    const uint32_t abase = smem_u32(sm + AS_OFF + sidx * ASTG_SZ);
    const uint32_t bbase = smem_u32(sm + BS_OFF + sidx * BSTG_SZ);
    const __half* bsrc = g_U16 + (size_t)k0 * A_ + at * 128;
    #pragma unroll
    for (int i = 0; i < 4; i++) {
        const int q = tid + i * 128;             // 0..511
        const int m = q >> 2, c = q & 3;
        cp_async16(abase + (uint32_t)(m * A_STRIDE + c * 16),
                   h16row0 + (size_t)m * D_ + k0 + c * 8);
        const int k = q >> 4, nc = q & 15;
        cp_async16(bbase + (uint32_t)(k * B_STRIDE + nc * 16),
                   bsrc + (size_t)k * A_ + nc * 8);
    }
    CP_COMMIT();
}

// ---------------------------------------------------------------------------
// scores: CTA = 128 bt-rows x A(1024) x K(1024), 128 threads (4 warps).
// Warp grid 2m x 2n, warp tile 64x64. Per g-step: all 16 ldmatrix issued
// up-front (both ks-halves), then 64 back-to-back MMAs — one LDS-latency
// exposure per g instead of eight.
// ---------------------------------------------------------------------------
__global__ void __launch_bounds__(128, 2) scores_mma_kernel(const float* __restrict__ v) {
    extern __shared__ char smc[];
    const int tid  = threadIdx.x;
    const int lane = tid & 31, wid = tid >> 5;
    const int wm = wid & 1, wn = wid >> 1;        // 2 m-warps x 2 n-warps
    const int g4 = lane >> 2, l4 = lane & 3;
    const int row0 = blockIdx.x * 128;
    const int b = row0 / T_;
    const __half* h16row0 = g_h16 + (size_t)row0 * D_;

    float* wsh = (float*)(smc + WS_OFF);
    float* vsh = (float*)(smc + VS_OFF);
    float* sch = (float*)(smc + SC_OFF);          // [2][128], bank per wn

    for (int i = tid; i < 1024; i += 128) {
        wsh[i] = g_ws[b * A_ + i];
        vsh[i] = v[i];
    }
    sch[tid] = 0.f;
    sch[128 + tid] = 0.f;

    const int frow  = (lane & 7) + ((lane >> 3) & 1) * 8;
    const int chalf = (lane >> 4) & 1;
    uint32_t a_rowoff[4];
    #pragma unroll
    for (int mi = 0; mi < 4; mi++)
        a_rowoff[mi] = (uint32_t)((wm * 64 + mi * 16 + frow) * A_STRIDE);
    const uint32_t bcol_base = (uint32_t)((wn * 8 + chalf) * 16);

    stage(smc, 0, h16row0, tid);
    stage(smc, 1, h16row0, tid);

    float C[4][8][4];

    for (int g = 0; g < NG; g++) {
        if ((g & 31) == 0) {
            #pragma unroll
            for (int mi = 0; mi < 4; mi++)
                #pragma unroll
                for (int ni = 0; ni < 8; ni++)
                    #pragma unroll
                    for (int q = 0; q < 4; q++) C[mi][ni][q] = 0.f;
        }

        if ((g & 1) == 0) {
            CP_WAIT0();                            // chunks g, g+1 landed
            __syncthreads();                       // ...and visible to all
            if (g + 2 < NG) stage(smc, g + 2, h16row0, tid);
            if (g + 3 < NG) stage(smc, g + 3, h16row0, tid);
        }

        const uint32_t abase = smem_u32(smc + AS_OFF + (g % NSTG) * ASTG_SZ);
        const uint32_t bbase = smem_u32(smc + BS_OFF + (g % NSTG) * BSTG_SZ);

        // --- issue ALL fragment loads for both ks-halves first ---
        uint32_t afr[2][4][4], bfr[2][4][4];
        #pragma unroll
        for (int hf = 0; hf < 2; hf++) {
            const int ks = hf * 16;
            const uint32_t acol = (uint32_t)(((ks >> 3) + chalf) * 16);
            #pragma unroll
            for (int mi = 0; mi < 4; mi++)
                ldsm_x4(afr[hf][mi], abase + a_rowoff[mi] + acol);
            const uint32_t brow = bbase + (uint32_t)((ks + frow) * B_STRIDE);
            #pragma unroll
            for (int p = 0; p < 4; p++)
                ldsm_x4_t(bfr[hf][p], brow + bcol_base + (uint32_t)(p * 32));
        }

        // --- 64 back-to-back MMAs ---
        #pragma unroll
        for (int hf = 0; hf < 2; hf++)
            #pragma unroll
            for (int p = 0; p < 4; p++)
                #pragma unroll
                for (int mi = 0; mi < 4; mi++) {
                    mma16816(C[mi][p * 2],     afr[hf][mi], bfr[hf][p]);
                    mma16816(C[mi][p * 2 + 1], afr[hf][mi], bfr[hf][p] + 2);
                }

        if ((g & 31) == 31) {
            const int at = g >> 5;
            float racc[4][2];
            #pragma unroll
            for (int mi = 0; mi < 4; mi++) { racc[mi][0] = 0.f; racc[mi][1] = 0.f; }
            #pragma unroll
            for (int ni = 0; ni < 8; ni++) {
                #pragma unroll
                for (int cb = 0; cb < 2; cb++) {
                    const int col = at * 128 + wn * 64 + ni * 8 + l4 * 2 + cb;
                    const float wsv = wsh[col];
                    const float vv  = vsh[col];
                    #pragma unroll
                    for (int mi = 0; mi < 4; mi++) {
                        racc[mi][0] += vv * tanh_fast(C[mi][ni][cb]     + wsv);
                        racc[mi][1] += vv * tanh_fast(C[mi][ni][cb + 2] + wsv);
                    }
                }
            }
            #pragma unroll
            for (int off = 1; off <= 2; off <<= 1) {
                #pragma unroll
                for (int mi = 0; mi < 4; mi++) {
                    racc[mi][0] += __shfl_xor_sync(0xffffffffu, racc[mi][0], off);
                    racc[mi][1] += __shfl_xor_sync(0xffffffffu, racc[mi][1], off);
                }
            }
            // each address owned by exactly one (wn, wm, mi, g4) thread
            if (l4 == 0) {
                float* bank = sch + wn * 128 + wm * 64;
                #pragma unroll
                for (int mi = 0; mi < 4; mi++) {
                    bank[mi * 16 + g4]     += racc[mi][0];
                    bank[mi * 16 + g4 + 8] += racc[mi][1];
                }
            }
        }
    }

    __syncthreads();
    g_scores[row0 + tid] = sch[tid] + sch[128 + tid];
}

// ---------------------------------------------------------------------------
// fp32 -> fp16 converters
// ---------------------------------------------------------------------------
__global__ __launch_bounds__(256) void conv_h_kernel(const float* __restrict__ h) {
    const size_t i = (size_t)blockIdx.x * 256 + threadIdx.x;
    const float4 val = ((const float4*)h)[i];
    __half2 lo = __floats2half2_rn(val.x, val.y);
    __half2 hi = __floats2half2_rn(val.z, val.w);
    ((uint2*)g_h16)[i] = make_uint2(*(uint32_t*)&lo, *(uint32_t*)&hi);
}
__global__ __launch_bounds__(256) void conv_U_kernel(const float* __restrict__ U) {
    const size_t i = (size_t)blockIdx.x * 256 + threadIdx.x;
    const float4 val = ((const float4*)U)[i];
    __half2 lo = __floats2half2_rn(val.x, val.y);
    __half2 hi = __floats2half2_rn(val.z, val.w);
    ((uint2*)g_U16)[i] = make_uint2(*(uint32_t*)&lo, *(uint32_t*)&hi);
}

// ---------------------------------------------------------------------------
__global__ __launch_bounds__(128) void ws_kernel(const float* __restrict__ s,
                                                 const float* __restrict__ W) {
    __shared__ float ssm[D_];
    int b = blockIdx.y;
    for (int i = threadIdx.x; i < D_; i += 128) ssm[i] = s[b * D_ + i];
    __syncthreads();
    int a = blockIdx.x * 128 + threadIdx.x;
    float acc = 0.f;
    #pragma unroll 8
    for (int d = 0; d < D_; d++) acc += ssm[d] * W[(size_t)d * A_ + a];
    g_ws[b * A_ + a] = acc;
}

__global__ __launch_bounds__(256) void softmax_kernel() {
    int b = blockIdx.x;
    __shared__ float red[256];
    float sum = 0.f;
    for (int t = threadIdx.x; t < T_; t += 256) {
        float e = expf(g_scores[b * T_ + t]);
        g_scores[b * T_ + t] = e;
        sum += e;
    }
    red[threadIdx.x] = sum;
    __syncthreads();
    for (int s = 128; s > 0; s >>= 1) {
        if (threadIdx.x < s) red[threadIdx.x] += red[threadIdx.x + s];
        __syncthreads();
    }
    if (threadIdx.x == 0) g_zinv[b] = 1.0f / red[0];
}

// 16-way t-split: grid (D/128, B, 16)
__global__ __launch_bounds__(128) void context_part_kernel(const float* __restrict__ h) {
    int b = blockIdx.y, tc = blockIdx.z;
    int d = blockIdx.x * 128 + threadIdx.x;
    const float* hb = h + (size_t)b * T_ * D_ + (size_t)tc * 128 * D_ + d;
    const float* eb = g_scores + b * T_ + tc * 128;
    float a0 = 0.f, a1 = 0.f, a2 = 0.f, a3 = 0.f;
    #pragma unroll 2
    for (int t = 0; t < 128; t += 4) {
        a0 += eb[t + 0] * hb[(size_t)(t + 0) * D_];
        a1 += eb[t + 1] * hb[(size_t)(t + 1) * D_];
        a2 += eb[t + 2] * hb[(size_t)(t + 2) * D_];
        a3 += eb[t + 3] * hb[(size_t)(t + 3) * D_];
    }
    g_cpart[((size_t)tc * B_ + b) * D_ + d] = ((a0 + a1) + (a2 + a3));
}

__global__ __launch_bounds__(256) void context_reduce_kernel(float* __restrict__ out) {
    int idx = blockIdx.x * 256 + threadIdx.x;
    float sum = 0.f;
    #pragma unroll
    for (int z = 0; z < 16; z++) sum += g_cpart[(size_t)z * B_ * D_ + idx];
    out[idx] = sum * g_zinv[idx >> 10];
}

// ---------------------------------------------------------------------------
extern "C" void kernel_launch(void* const* d_in, const int* in_sizes, int n_in,
                              void* d_out, int out_size) {
    const float* s  = (const float*)d_in[0];
    const float* h  = (const float*)d_in[1];
    const float* Wa = (const float*)d_in[2];
    const float* Ua = (const float*)d_in[3];
    const float* va = (const float*)d_in[4];
    float* out = (float*)d_out;

    cudaFuncSetAttribute(scores_mma_kernel,
                         cudaFuncAttributeMaxDynamicSharedMemorySize, SMEM_SZ);

    conv_U_kernel<<<(D_ * A_ / 4) / 256, 256>>>(Ua);
    conv_h_kernel<<<(int)(((size_t)B_ * T_ * D_ / 4) / 256), 256>>>(h);
    ws_kernel<<<dim3(A_ / 128, B_), 128>>>(s, Wa);
    scores_mma_kernel<<<(B_ * T_) / 128, 128, SMEM_SZ>>>(va);
    softmax_kernel<<<B_, 256>>>();
    context_part_kernel<<<dim3(D_ / 128, B_, 16), 128>>>(h);
    context_reduce_kernel<<<128, 256>>>(out);
}

// round 13
// speedup vs baseline: 1.0688x; 1.0688x over previous
#include <cuda_runtime.h>
#include <cuda_fp16.h>
#include <cstdint>
#include <math.h>

#define B_  32
#define T_  2048
#define D_  1024
#define A_  1024

// ---------------- scratch ---------------------------------------------------
__device__ float  g_ws[B_ * A_];
__device__ float  g_scores[B_ * T_];     // exp(score) after scores kernel
__device__ float  g_esum[B_];            // sum_t exp(score)  (zeroed in conv_U)
__device__ float  g_cpart[16 * B_ * D_];
__device__ __half g_h16[(size_t)B_ * T_ * D_];   // 128 MB
__device__ __half g_U16[(size_t)D_ * A_];        // 2 MB

// ---------------- helpers ---------------------------------------------------
__device__ __forceinline__ uint32_t smem_u32(const void* p) {
    uint32_t a;
    asm("{ .reg .u64 t; cvta.to.shared.u64 t, %1; cvt.u32.u64 %0, t; }" : "=r"(a) : "l"(p));
    return a;
}
__device__ __forceinline__ void cp_async16(uint32_t dst, const void* src) {
    asm volatile("cp.async.cg.shared.global [%0], [%1], 16;\n" :: "r"(dst), "l"(src) : "memory");
}
#define CP_COMMIT() asm volatile("cp.async.commit_group;\n" ::: "memory")
#define CP_WAIT0()  asm volatile("cp.async.wait_group 0;\n" ::: "memory")

__device__ __forceinline__ void ldsm_x4(uint32_t* r, uint32_t addr) {
    asm volatile("ldmatrix.sync.aligned.m8n8.x4.shared.b16 {%0,%1,%2,%3}, [%4];"
        : "=r"(r[0]), "=r"(r[1]), "=r"(r[2]), "=r"(r[3]) : "r"(addr));
}
__device__ __forceinline__ void ldsm_x4_t(uint32_t* r, uint32_t addr) {
    asm volatile("ldmatrix.sync.aligned.m8n8.x4.trans.shared.b16 {%0,%1,%2,%3}, [%4];"
        : "=r"(r[0]), "=r"(r[1]), "=r"(r[2]), "=r"(r[3]) : "r"(addr));
}
__device__ __forceinline__ void mma16816(float* c, const uint32_t* a, const uint32_t* b) {
    asm volatile(
        "mma.sync.aligned.m16n8k16.row.col.f32.f16.f16.f32 "
        "{%0,%1,%2,%3}, {%4,%5,%6,%7}, {%8,%9}, {%0,%1,%2,%3};"
        : "+f"(c[0]), "+f"(c[1]), "+f"(c[2]), "+f"(c[3])
        : "r"(a[0]), "r"(a[1]), "r"(a[2]), "r"(a[3]), "r"(b[0]), "r"(b[1]));
}
__device__ __forceinline__ float tanh_fast(float x) {
    float y;
    asm("tanh.approx.f32 %0, %1;" : "=f"(y) : "f"(x));
    return y;
}

// ---------------- smem layout (bytes) ---------------------------------------
#define NSTG     4
#define A_STRIDE 112
#define B_STRIDE 272
#define ASTG_SZ  (128 * A_STRIDE)                // 14336
#define BSTG_SZ  (32 * B_STRIDE)                 // 8704
#define AS_OFF   0
#define BS_OFF   (NSTG * ASTG_SZ)                // 57344
#define WS_OFF   (BS_OFF + NSTG * BSTG_SZ)       // 92160
#define VS_OFF   (WS_OFF + 4096)                 // 96256
#define SC_OFF   (VS_OFF + 4096)                 // 100352  (2 banks x 128 floats)
#define SMEM_SZ  (SC_OFF + 1024)                 // 101376

#define NG 256   // 8 a-tiles x 32 k-chunks

// stage chunk g = at*32 + kc  (128 threads: 4 iters of 128 for A and B each)
__device__ __forceinline__ void stage(char* sm, int g, const __half* __restrict__ h16row0,
                                      int tid) {
    const int sidx = g % NSTG;
    const int kc = g & 31, at = g >> 5;
    const int k0 = kc * 32;
    const uint32_t abase = smem_u32(sm + AS_OFF + sidx * ASTG_SZ);
    const uint32_t bbase = smem_u32(sm + BS_OFF + sidx * BSTG_SZ);
    const __half* bsrc = g_U16 + (size_t)k0 * A_ + at * 128;
    #pragma unroll
    for (int i = 0; i < 4; i++) {
        const int q = tid + i * 128;             // 0..511
        const int m = q >> 2, c = q & 3;
        cp_async16(abase + (uint32_t)(m * A_STRIDE + c * 16),
                   h16row0 + (size_t)m * D_ + k0 + c * 8);
        const int k = q >> 4, nc = q & 15;
        cp_async16(bbase + (uint32_t)(k * B_STRIDE + nc * 16),
                   bsrc + (size_t)k * A_ + nc * 8);
    }
    CP_COMMIT();
}

// ---------------------------------------------------------------------------
// scores: CTA = 128 bt-rows x A(1024) x K(1024), 128 threads (4 warps).
// Warp grid 2m x 2n, warp tile 64x64. g-loop written as explicit pairs.
// Epilogue fuses tanh + v-dot; final store fuses exp + block-sum -> g_esum.
// ---------------------------------------------------------------------------
__global__ void __launch_bounds__(128, 2) scores_mma_kernel(const float* __restrict__ v) {
    extern __shared__ char smc[];
    const int tid  = threadIdx.x;
    const int lane = tid & 31, wid = tid >> 5;
    const int wm = wid & 1, wn = wid >> 1;        // 2 m-warps x 2 n-warps
    const int g4 = lane >> 2, l4 = lane & 3;
    const int row0 = blockIdx.x * 128;
    const int b = row0 / T_;
    const __half* h16row0 = g_h16 + (size_t)row0 * D_;

    float* wsh = (float*)(smc + WS_OFF);
    float* vsh = (float*)(smc + VS_OFF);
    float* sch = (float*)(smc + SC_OFF);          // [2][128], bank per wn

    for (int i = tid; i < 1024; i += 128) {
        wsh[i] = g_ws[b * A_ + i];
        vsh[i] = v[i];
    }
    sch[tid] = 0.f;
    sch[128 + tid] = 0.f;

    const int frow  = (lane & 7) + ((lane >> 3) & 1) * 8;
    const int chalf = (lane >> 4) & 1;
    uint32_t a_rowoff[4];
    #pragma unroll
    for (int mi = 0; mi < 4; mi++)
        a_rowoff[mi] = (uint32_t)((wm * 64 + mi * 16 + frow) * A_STRIDE);
    const uint32_t bcol_base = (uint32_t)((wn * 8 + chalf) * 16);

    stage(smc, 0, h16row0, tid);
    stage(smc, 1, h16row0, tid);

    float C[4][8][4];

    auto body = [&](int g) {
        const uint32_t abase = smem_u32(smc + AS_OFF + (g % NSTG) * ASTG_SZ);
        const uint32_t bbase = smem_u32(smc + BS_OFF + (g % NSTG) * BSTG_SZ);
        uint32_t afr[2][4][4], bfr[2][4][4];
        #pragma unroll
        for (int hf = 0; hf < 2; hf++) {
            const int ks = hf * 16;
            const uint32_t acol = (uint32_t)(((ks >> 3) + chalf) * 16);
            #pragma unroll
            for (int mi = 0; mi < 4; mi++)
                ldsm_x4(afr[hf][mi], abase + a_rowoff[mi] + acol);
            const uint32_t brow = bbase + (uint32_t)((ks + frow) * B_STRIDE);
            #pragma unroll
            for (int p = 0; p < 4; p++)
                ldsm_x4_t(bfr[hf][p], brow + bcol_base + (uint32_t)(p * 32));
        }
        #pragma unroll
        for (int hf = 0; hf < 2; hf++)
            #pragma unroll
            for (int p = 0; p < 4; p++)
                #pragma unroll
                for (int mi = 0; mi < 4; mi++) {
                    mma16816(C[mi][p * 2],     afr[hf][mi], bfr[hf][p]);
                    mma16816(C[mi][p * 2 + 1], afr[hf][mi], bfr[hf][p] + 2);
                }
    };

    for (int gp = 0; gp < 128; gp++) {
        const int g0 = gp * 2;

        if ((gp & 15) == 0) {
            #pragma unroll
            for (int mi = 0; mi < 4; mi++)
                #pragma unroll
                for (int ni = 0; ni < 8; ni++)
                    #pragma unroll
                    for (int q = 0; q < 4; q++) C[mi][ni][q] = 0.f;
        }

        CP_WAIT0();                                // chunks g0, g0+1 landed
        __syncthreads();                           // ...and visible to all
        if (g0 + 2 < NG) stage(smc, g0 + 2, h16row0, tid);
        if (g0 + 3 < NG) stage(smc, g0 + 3, h16row0, tid);

        body(g0);
        body(g0 + 1);

        if ((gp & 15) == 15) {
            const int at = g0 >> 5;
            float racc[4][2];
            #pragma unroll
            for (int mi = 0; mi < 4; mi++) { racc[mi][0] = 0.f; racc[mi][1] = 0.f; }
            #pragma unroll
            for (int ni = 0; ni < 8; ni++) {
                #pragma unroll
                for (int cb = 0; cb < 2; cb++) {
                    const int col = at * 128 + wn * 64 + ni * 8 + l4 * 2 + cb;
                    const float wsv = wsh[col];
                    const float vv  = vsh[col];
                    #pragma unroll
                    for (int mi = 0; mi < 4; mi++) {
                        racc[mi][0] += vv * tanh_fast(C[mi][ni][cb]     + wsv);
                        racc[mi][1] += vv * tanh_fast(C[mi][ni][cb + 2] + wsv);
                    }
                }
            }
            #pragma unroll
            for (int off = 1; off <= 2; off <<= 1) {
                #pragma unroll
                for (int mi = 0; mi < 4; mi++) {
                    racc[mi][0] += __shfl_xor_sync(0xffffffffu, racc[mi][0], off);
                    racc[mi][1] += __shfl_xor_sync(0xffffffffu, racc[mi][1], off);
                }
            }
            if (l4 == 0) {
                float* bank = sch + wn * 128 + wm * 64;
                #pragma unroll
                for (int mi = 0; mi < 4; mi++) {
                    bank[mi * 16 + g4]     += racc[mi][0];
                    bank[mi * 16 + g4 + 8] += racc[mi][1];
                }
            }
        }
    }

    // fused exp + per-b partial sum
    __syncthreads();
    const float e = expf(sch[tid] + sch[128 + tid]);
    g_scores[row0 + tid] = e;
    __syncthreads();
    sch[tid] = e;
    __syncthreads();
    #pragma unroll
    for (int s = 64; s > 0; s >>= 1) {
        if (tid < s) sch[tid] += sch[tid + s];
        __syncthreads();
    }
    if (tid == 0) atomicAdd(&g_esum[b], sch[0]);
}

// ---------------------------------------------------------------------------
// fp32 -> fp16 converters (conv_U also zeroes g_esum; runs before scores)
// ---------------------------------------------------------------------------
__global__ __launch_bounds__(256) void conv_h_kernel(const float* __restrict__ h) {
    const size_t i = (size_t)blockIdx.x * 256 + threadIdx.x;
    const float4 val = ((const float4*)h)[i];
    __half2 lo = __floats2half2_rn(val.x, val.y);
    __half2 hi = __floats2half2_rn(val.z, val.w);
    ((uint2*)g_h16)[i] = make_uint2(*(uint32_t*)&lo, *(uint32_t*)&hi);
}
__global__ __launch_bounds__(256) void conv_U_kernel(const float* __restrict__ U) {
    if (blockIdx.x == 0 && threadIdx.x < B_) g_esum[threadIdx.x] = 0.f;
    const size_t i = (size_t)blockIdx.x * 256 + threadIdx.x;
    const float4 val = ((const float4*)U)[i];
    __half2 lo = __floats2half2_rn(val.x, val.y);
    __half2 hi = __floats2half2_rn(val.z, val.w);
    ((uint2*)g_U16)[i] = make_uint2(*(uint32_t*)&lo, *(uint32_t*)&hi);
}

// ---------------------------------------------------------------------------
__global__ __launch_bounds__(128) void ws_kernel(const float* __restrict__ s,
                                                 const float* __restrict__ W) {
    __shared__ float ssm[D_];
    int b = blockIdx.y;
    for (int i = threadIdx.x; i < D_; i += 128) ssm[i] = s[b * D_ + i];
    __syncthreads();
    int a = blockIdx.x * 128 + threadIdx.x;
    float acc = 0.f;
    #pragma unroll 8
    for (int d = 0; d < D_; d++) acc += ssm[d] * W[(size_t)d * A_ + a];
    g_ws[b * A_ + a] = acc;
}

// context pass 1: reads fp16 h (half the DRAM bytes). 16-way t-split.
// grid (D/256, B, 16), 128 threads; each thread owns one half2 (2 d's).
__global__ __launch_bounds__(128) void context_part_kernel() {
    const int b = blockIdx.y, tc = blockIdx.z;
    const int d2 = blockIdx.x * 128 + threadIdx.x;          // 0..511 half2 idx
    const __half2* hb = (const __half2*)(g_h16 + (size_t)b * T_ * D_
                                         + (size_t)tc * 128 * D_) + d2;
    const float* eb = g_scores + b * T_ + tc * 128;
    float2 a0 = {0.f, 0.f}, a1 = {0.f, 0.f};
    #pragma unroll 4
    for (int t = 0; t < 128; t += 2) {
        const float2 h0 = __half22float2(hb[(size_t)t * (D_ / 2)]);
        const float2 h1 = __half22float2(hb[(size_t)(t + 1) * (D_ / 2)]);
        const float e0 = eb[t], e1 = eb[t + 1];
        a0.x += e0 * h0.x; a0.y += e0 * h0.y;
        a1.x += e1 * h1.x; a1.y += e1 * h1.y;
    }
    float2 r; r.x = a0.x + a1.x; r.y = a0.y + a1.y;
    ((float2*)(g_cpart + ((size_t)tc * B_ + b) * D_))[d2] = r;
}

__global__ __launch_bounds__(256) void context_reduce_kernel(float* __restrict__ out) {
    int idx = blockIdx.x * 256 + threadIdx.x;
    float sum = 0.f;
    #pragma unroll
    for (int z = 0; z < 16; z++) sum += g_cpart[(size_t)z * B_ * D_ + idx];
    out[idx] = sum * (1.0f / g_esum[idx >> 10]);
}

// ---------------------------------------------------------------------------
extern "C" void kernel_launch(void* const* d_in, const int* in_sizes, int n_in,
                              void* d_out, int out_size) {
    const float* s  = (const float*)d_in[0];
    const float* h  = (const float*)d_in[1];
    const float* Wa = (const float*)d_in[2];
    const float* Ua = (const float*)d_in[3];
    const float* va = (const float*)d_in[4];
    float* out = (float*)d_out;

    cudaFuncSetAttribute(scores_mma_kernel,
                         cudaFuncAttributeMaxDynamicSharedMemorySize, SMEM_SZ);

    conv_U_kernel<<<(D_ * A_ / 4) / 256, 256>>>(Ua);
    conv_h_kernel<<<(int)(((size_t)B_ * T_ * D_ / 4) / 256), 256>>>(h);
    ws_kernel<<<dim3(A_ / 128, B_), 128>>>(s, Wa);
    scores_mma_kernel<<<(B_ * T_) / 128, 128, SMEM_SZ>>>(va);
    context_part_kernel<<<dim3(D_ / 256, B_, 16), 128>>>();
    context_reduce_kernel<<<128, 256>>>(out);
}

// round 14
// speedup vs baseline: 1.1782x; 1.1024x over previous
#include <cuda_runtime.h>
#include <cuda_fp16.h>
#include <cstdint>
#include <math.h>

#define B_  32
#define T_  2048
#define D_  1024
#define A_  1024
#define ASPLIT 4                 // a-dim split: each scores CTA does 2 a-tiles

// ---------------- scratch ---------------------------------------------------
__device__ float  g_ws[B_ * A_];
__device__ float  g_scores[B_ * T_];     // zeroed by conv_U; atomicAdd partials; exp'd by softmax
__device__ float  g_esum[B_];
__device__ float  g_cpart[16 * B_ * D_];
__device__ __half g_h16[(size_t)B_ * T_ * D_];   // 128 MB
__device__ __half g_U16[(size_t)D_ * A_];        // 2 MB

// ---------------- helpers ---------------------------------------------------
__device__ __forceinline__ uint32_t smem_u32(const void* p) {
    uint32_t a;
    asm("{ .reg .u64 t; cvta.to.shared.u64 t, %1; cvt.u32.u64 %0, t; }" : "=r"(a) : "l"(p));
    return a;
}
__device__ __forceinline__ void cp_async16(uint32_t dst, const void* src) {
    asm volatile("cp.async.cg.shared.global [%0], [%1], 16;\n" :: "r"(dst), "l"(src) : "memory");
}
#define CP_COMMIT() asm volatile("cp.async.commit_group;\n" ::: "memory")
#define CP_WAIT0()  asm volatile("cp.async.wait_group 0;\n" ::: "memory")

__device__ __forceinline__ void ldsm_x4(uint32_t* r, uint32_t addr) {
    asm volatile("ldmatrix.sync.aligned.m8n8.x4.shared.b16 {%0,%1,%2,%3}, [%4];"
        : "=r"(r[0]), "=r"(r[1]), "=r"(r[2]), "=r"(r[3]) : "r"(addr));
}
__device__ __forceinline__ void ldsm_x4_t(uint32_t* r, uint32_t addr) {
    asm volatile("ldmatrix.sync.aligned.m8n8.x4.trans.shared.b16 {%0,%1,%2,%3}, [%4];"
        : "=r"(r[0]), "=r"(r[1]), "=r"(r[2]), "=r"(r[3]) : "r"(addr));
}
__device__ __forceinline__ void mma16816(float* c, const uint32_t* a, const uint32_t* b) {
    asm volatile(
        "mma.sync.aligned.m16n8k16.row.col.f32.f16.f16.f32 "
        "{%0,%1,%2,%3}, {%4,%5,%6,%7}, {%8,%9}, {%0,%1,%2,%3};"
        : "+f"(c[0]), "+f"(c[1]), "+f"(c[2]), "+f"(c[3])
        : "r"(a[0]), "r"(a[1]), "r"(a[2]), "r"(a[3]), "r"(b[0]), "r"(b[1]));
}
__device__ __forceinline__ float tanh_fast(float x) {
    float y;
    asm("tanh.approx.f32 %0, %1;" : "=f"(y) : "f"(x));
    return y;
}

// ---------------- smem layout (bytes) ---------------------------------------
#define NSTG     4
#define A_STRIDE 112
#define B_STRIDE 272
#define ASTG_SZ  (128 * A_STRIDE)                // 14336
#define BSTG_SZ  (32 * B_STRIDE)                 // 8704
#define AS_OFF   0
#define BS_OFF   (NSTG * ASTG_SZ)                // 57344
#define WS_OFF   (BS_OFF + NSTG * BSTG_SZ)       // 92160  (256 floats used)
#define VS_OFF   (WS_OFF + 4096)                 // 96256  (256 floats used)
#define SC_OFF   (VS_OFF + 4096)                 // 100352 (2 banks x 128 floats)
#define SMEM_SZ  (SC_OFF + 1024)                 // 101376

#define NG 64    // per CTA: 2 a-tiles x 32 k-chunks

// stage chunk g = at_local*32 + kc for this CTA's a-slice
__device__ __forceinline__ void stage(char* sm, int g, const __half* __restrict__ h16row0,
                                      const __half* __restrict__ Uslice, int tid) {
    const int sidx = g % NSTG;
    const int kc = g & 31, at = g >> 5;          // at in {0,1}
    const int k0 = kc * 32;
    const uint32_t abase = smem_u32(sm + AS_OFF + sidx * ASTG_SZ);
    const uint32_t bbase = smem_u32(sm + BS_OFF + sidx * BSTG_SZ);
    const __half* bsrc = Uslice + (size_t)k0 * A_ + at * 128;
    #pragma unroll
    for (int i = 0; i < 4; i++) {
        const int q = tid + i * 128;             // 0..511
        const int m = q >> 2, c = q & 3;
        cp_async16(abase + (uint32_t)(m * A_STRIDE + c * 16),
                   h16row0 + (size_t)m * D_ + k0 + c * 8);
        const int k = q >> 4, nc = q & 15;
        cp_async16(bbase + (uint32_t)(k * B_STRIDE + nc * 16),
                   bsrc + (size_t)k * A_ + nc * 8);
    }
    CP_COMMIT();
}

// ---------------------------------------------------------------------------
// scores: grid = 512 tiles x ASPLIT slices. CTA = 128 bt-rows x 256 a-cols
// (2 a-tiles) x K(1024); partial scores accumulated to g_scores via atomicAdd.
// ---------------------------------------------------------------------------
__global__ void __launch_bounds__(128, 2) scores_mma_kernel(const float* __restrict__ v) {
    extern __shared__ char smc[];
    const int tid  = threadIdx.x;
    const int lane = tid & 31, wid = tid >> 5;
    const int wm = wid & 1, wn = wid >> 1;        // 2 m-warps x 2 n-warps
    const int g4 = lane >> 2, l4 = lane & 3;
    const int tile   = blockIdx.x >> 2;
    const int aslice = blockIdx.x & 3;
    const int row0 = tile * 128;
    const int b = row0 / T_;
    const int a0 = aslice * 256;                  // this CTA's a-range base
    const __half* h16row0 = g_h16 + (size_t)row0 * D_;
    const __half* Uslice  = g_U16 + a0;

    float* wsh = (float*)(smc + WS_OFF);
    float* vsh = (float*)(smc + VS_OFF);
    float* sch = (float*)(smc + SC_OFF);          // [2][128], bank per wn

    if (tid < 128) {                              // 256 entries, 2 per thread
        wsh[tid]       = g_ws[b * A_ + a0 + tid];
        wsh[tid + 128] = g_ws[b * A_ + a0 + tid + 128];
        vsh[tid]       = v[a0 + tid];
        vsh[tid + 128] = v[a0 + tid + 128];
    }
    sch[tid] = 0.f;
    sch[128 + tid] = 0.f;

    const int frow  = (lane & 7) + ((lane >> 3) & 1) * 8;
    const int chalf = (lane >> 4) & 1;
    uint32_t a_rowoff[4];
    #pragma unroll
    for (int mi = 0; mi < 4; mi++)
        a_rowoff[mi] = (uint32_t)((wm * 64 + mi * 16 + frow) * A_STRIDE);
    const uint32_t bcol_base = (uint32_t)((wn * 8 + chalf) * 16);

    stage(smc, 0, h16row0, Uslice, tid);
    stage(smc, 1, h16row0, Uslice, tid);

    float C[4][8][4];

    auto body = [&](int g) {
        const uint32_t abase = smem_u32(smc + AS_OFF + (g % NSTG) * ASTG_SZ);
        const uint32_t bbase = smem_u32(smc + BS_OFF + (g % NSTG) * BSTG_SZ);
        uint32_t afr[2][4][4], bfr[2][4][4];
        #pragma unroll
        for (int hf = 0; hf < 2; hf++) {
            const int ks = hf * 16;
            const uint32_t acol = (uint32_t)(((ks >> 3) + chalf) * 16);
            #pragma unroll
            for (int mi = 0; mi < 4; mi++)
                ldsm_x4(afr[hf][mi], abase + a_rowoff[mi] + acol);
            const uint32_t brow = bbase + (uint32_t)((ks + frow) * B_STRIDE);
            #pragma unroll
            for (int p = 0; p < 4; p++)
                ldsm_x4_t(bfr[hf][p], brow + bcol_base + (uint32_t)(p * 32));
        }
        #pragma unroll
        for (int hf = 0; hf < 2; hf++)
            #pragma unroll
            for (int p = 0; p < 4; p++)
                #pragma unroll
                for (int mi = 0; mi < 4; mi++) {
                    mma16816(C[mi][p * 2],     afr[hf][mi], bfr[hf][p]);
                    mma16816(C[mi][p * 2 + 1], afr[hf][mi], bfr[hf][p] + 2);
                }
    };

    for (int gp = 0; gp < NG / 2; gp++) {         // 32 pairs
        const int g0 = gp * 2;

        if ((gp & 15) == 0) {
            #pragma unroll
            for (int mi = 0; mi < 4; mi++)
                #pragma unroll
                for (int ni = 0; ni < 8; ni++)
                    #pragma unroll
                    for (int q = 0; q < 4; q++) C[mi][ni][q] = 0.f;
        }

        CP_WAIT0();                                // chunks g0, g0+1 landed
        __syncthreads();                           // ...and visible to all
        if (g0 + 2 < NG) stage(smc, g0 + 2, h16row0, Uslice, tid);
        if (g0 + 3 < NG) stage(smc, g0 + 3, h16row0, Uslice, tid);

        body(g0);
        body(g0 + 1);

        if ((gp & 15) == 15) {
            const int at = g0 >> 5;                // local a-tile 0/1
            float racc[4][2];
            #pragma unroll
            for (int mi = 0; mi < 4; mi++) { racc[mi][0] = 0.f; racc[mi][1] = 0.f; }
            #pragma unroll
            for (int ni = 0; ni < 8; ni++) {
                #pragma unroll
                for (int cb = 0; cb < 2; cb++) {
                    const int col = at * 128 + wn * 64 + ni * 8 + l4 * 2 + cb;
                    const float wsv = wsh[col];
                    const float vv  = vsh[col];
                    #pragma unroll
                    for (int mi = 0; mi < 4; mi++) {
                        racc[mi][0] += vv * tanh_fast(C[mi][ni][cb]     + wsv);
                        racc[mi][1] += vv * tanh_fast(C[mi][ni][cb + 2] + wsv);
                    }
                }
            }
            #pragma unroll
            for (int off = 1; off <= 2; off <<= 1) {
                #pragma unroll
                for (int mi = 0; mi < 4; mi++) {
                    racc[mi][0] += __shfl_xor_sync(0xffffffffu, racc[mi][0], off);
                    racc[mi][1] += __shfl_xor_sync(0xffffffffu, racc[mi][1], off);
                }
            }
            if (l4 == 0) {
                float* bank = sch + wn * 128 + wm * 64;
                #pragma unroll
                for (int mi = 0; mi < 4; mi++) {
                    bank[mi * 16 + g4]     += racc[mi][0];
                    bank[mi * 16 + g4 + 8] += racc[mi][1];
                }
            }
        }
    }

    __syncthreads();
    atomicAdd(&g_scores[row0 + tid], sch[tid] + sch[128 + tid]);
}

// ---------------------------------------------------------------------------
// fp32 -> fp16 converters (conv_U also zeroes g_scores; runs before scores)
// ---------------------------------------------------------------------------
__global__ __launch_bounds__(256) void conv_h_kernel(const float* __restrict__ h) {
    const size_t i = (size_t)blockIdx.x * 256 + threadIdx.x;
    const float4 val = ((const float4*)h)[i];
    __half2 lo = __floats2half2_rn(val.x, val.y);
    __half2 hi = __floats2half2_rn(val.z, val.w);
    ((uint2*)g_h16)[i] = make_uint2(*(uint32_t*)&lo, *(uint32_t*)&hi);
}
__global__ __launch_bounds__(256) void conv_U_kernel(const float* __restrict__ U) {
    const size_t i = (size_t)blockIdx.x * 256 + threadIdx.x;
    if (i < B_ * T_) g_scores[i] = 0.f;          // grid covers 262144 >= 65536
    const float4 val = ((const float4*)U)[i];
    __half2 lo = __floats2half2_rn(val.x, val.y);
    __half2 hi = __floats2half2_rn(val.z, val.w);
    ((uint2*)g_U16)[i] = make_uint2(*(uint32_t*)&lo, *(uint32_t*)&hi);
}

// ---------------------------------------------------------------------------
__global__ __launch_bounds__(128) void ws_kernel(const float* __restrict__ s,
                                                 const float* __restrict__ W) {
    __shared__ float ssm[D_];
    int b = blockIdx.y;
    for (int i = threadIdx.x; i < D_; i += 128) ssm[i] = s[b * D_ + i];
    __syncthreads();
    int a = blockIdx.x * 128 + threadIdx.x;
    float acc = 0.f;
    #pragma unroll 8
    for (int d = 0; d < D_; d++) acc += ssm[d] * W[(size_t)d * A_ + a];
    g_ws[b * A_ + a] = acc;
}

__global__ __launch_bounds__(256) void softmax_kernel() {
    int b = blockIdx.x;
    __shared__ float red[256];
    float sum = 0.f;
    for (int t = threadIdx.x; t < T_; t += 256) {
        float e = expf(g_scores[b * T_ + t]);
        g_scores[b * T_ + t] = e;
        sum += e;
    }
    red[threadIdx.x] = sum;
    __syncthreads();
    for (int s = 128; s > 0; s >>= 1) {
        if (threadIdx.x < s) red[threadIdx.x] += red[threadIdx.x + s];
        __syncthreads();
    }
    if (threadIdx.x == 0) g_esum[b] = red[0];
}

// context pass 1: reads fp16 h. 16-way t-split. grid (D/256, B, 16).
__global__ __launch_bounds__(128) void context_part_kernel() {
    const int b = blockIdx.y, tc = blockIdx.z;
    const int d2 = blockIdx.x * 128 + threadIdx.x;          // half2 idx
    const __half2* hb = (const __half2*)(g_h16 + (size_t)b * T_ * D_
                                         + (size_t)tc * 128 * D_) + d2;
    const float* eb = g_scores + b * T_ + tc * 128;
    float2 a0 = {0.f, 0.f}, a1 = {0.f, 0.f};
    #pragma unroll 4
    for (int t = 0; t < 128; t += 2) {
        const float2 h0 = __half22float2(hb[(size_t)t * (D_ / 2)]);
        const float2 h1 = __half22float2(hb[(size_t)(t + 1) * (D_ / 2)]);
        const float e0 = eb[t], e1 = eb[t + 1];
        a0.x += e0 * h0.x; a0.y += e0 * h0.y;
        a1.x += e1 * h1.x; a1.y += e1 * h1.y;
    }
    float2 r; r.x = a0.x + a1.x; r.y = a0.y + a1.y;
    ((float2*)(g_cpart + ((size_t)tc * B_ + b) * D_))[d2] = r;
}

__global__ __launch_bounds__(256) void context_reduce_kernel(float* __restrict__ out) {
    int idx = blockIdx.x * 256 + threadIdx.x;
    float sum = 0.f;
    #pragma unroll
    for (int z = 0; z < 16; z++) sum += g_cpart[(size_t)z * B_ * D_ + idx];
    out[idx] = sum * (1.0f / g_esum[idx >> 10]);
}

// ---------------------------------------------------------------------------
extern "C" void kernel_launch(void* const* d_in, const int* in_sizes, int n_in,
                              void* d_out, int out_size) {
    const float* s  = (const float*)d_in[0];
    const float* h  = (const float*)d_in[1];
    const float* Wa = (const float*)d_in[2];
    const float* Ua = (const float*)d_in[3];
    const float* va = (const float*)d_in[4];
    float* out = (float*)d_out;

    cudaFuncSetAttribute(scores_mma_kernel,
                         cudaFuncAttributeMaxDynamicSharedMemorySize, SMEM_SZ);

    conv_U_kernel<<<(D_ * A_ / 4) / 256, 256>>>(Ua);
    conv_h_kernel<<<(int)(((size_t)B_ * T_ * D_ / 4) / 256), 256>>>(h);
    ws_kernel<<<dim3(A_ / 128, B_), 128>>>(s, Wa);
    scores_mma_kernel<<<(B_ * T_ / 128) * ASPLIT, 128, SMEM_SZ>>>(va);
    softmax_kernel<<<B_, 256>>>();
    context_part_kernel<<<dim3(D_ / 256, B_, 16), 128>>>();
    context_reduce_kernel<<<128, 256>>>(out);
}